// round 3
// baseline (speedup 1.0000x reference)
#include <cuda_runtime.h>
#include <math.h>

#define N_NODES  100000
#define N_EDGES  1600000
#define D        128
#define N_GRAPHS 512
#define N_CLASS  10
#define BN_EPS   1e-5f

#define NT   ((size_t)N_NODES * D)      // 12.8M floats
#define NT4  (NT / 4)                   // 3.2M float4

// Scratch (allocation-free: __device__ globals)
__device__ float g_bufA[NT];            // agg1, then agg2
__device__ float g_bufB[NT];            // z1
__device__ float g_pooled[N_GRAPHS * D];
__device__ float g_scale[D];
__device__ float g_shift[D];

// ---------------------------------------------------------------------------
// init: g_bufA = src (self-loop term of aggregation)
// ---------------------------------------------------------------------------
__global__ void init_agg_ext(const float4* __restrict__ src4) {
    size_t i = (size_t)blockIdx.x * blockDim.x + threadIdx.x;
    if (i < NT4) ((float4*)g_bufA)[i] = src4[i];
}
__global__ void init_agg_fromB() {
    size_t i = (size_t)blockIdx.x * blockDim.x + threadIdx.x;
    if (i < NT4) ((float4*)g_bufA)[i] = ((const float4*)g_bufB)[i];
}
__global__ void zero_pooled() {
    int i = blockIdx.x * blockDim.x + threadIdx.x;
    if (i < N_GRAPHS * D) g_pooled[i] = 0.f;
}

// ---------------------------------------------------------------------------
// Edge scatter-add: g_bufA[dst] += h[src], one warp per edge (128 floats)
// SRC==0: h = external pointer (x). SRC==1: h = g_bufB (z1).
// ---------------------------------------------------------------------------
template<int SRC>
__global__ void edge_agg(const float* __restrict__ hext,
                         const int* __restrict__ src,
                         const int* __restrict__ dst) {
    int e = blockIdx.x * (blockDim.x >> 5) + (threadIdx.x >> 5);
    if (e >= N_EDGES) return;
    const float* h = (SRC == 0) ? hext : g_bufB;
    int lane = threadIdx.x & 31;
    int s = __ldg(src + e);
    int d = __ldg(dst + e);
    float4 v = ((const float4*)(h + (size_t)s * D))[lane];
    float* o = g_bufA + (size_t)d * D + lane * 4;
    atomicAdd(o + 0, v.x);
    atomicAdd(o + 1, v.y);
    atomicAdd(o + 2, v.z);
    atomicAdd(o + 3, v.w);
}

// ---------------------------------------------------------------------------
// GEMM: [M=100000,128] @ [128,128] + bias, tiled 64x128 per block, 256 thr.
// MODE 0: out = relu(.) -> g_bufB
// MODE 1: out (no relu) pooled by sorted idx -> atomicAdd g_pooled (few atomics
//         per block thanks to in-block segment reduction over sorted idx)
// ---------------------------------------------------------------------------
template<int MODE>
__global__ __launch_bounds__(256)
void gemm128(const float* __restrict__ W, const float* __restrict__ bias,
             const int* __restrict__ idx) {
    __shared__ float sA[64][16];
    __shared__ float sW[16][128];
    __shared__ float sOut[MODE == 1 ? 64 * 128 : 1];
    __shared__ int   sIdx[MODE == 1 ? 64 : 1];

    const float* A = g_bufA;
    int tid = threadIdx.x;
    int tx = tid & 15;          // N index base (cols tx + 16*j)
    int ty = tid >> 4;          // M index base (rows ty + 16*i)
    int row0 = blockIdx.x * 64;

    float acc[4][8];
    #pragma unroll
    for (int i = 0; i < 4; i++)
        #pragma unroll
        for (int j = 0; j < 8; j++) acc[i][j] = 0.f;

    for (int ko = 0; ko < D; ko += 16) {
        // load A tile: 64 rows x 16 cols, one float4 per thread
        {
            int r = tid >> 2;
            int v = (tid & 3) * 4;
            int grow = row0 + r;
            float4 t = make_float4(0.f, 0.f, 0.f, 0.f);
            if (grow < N_NODES)
                t = *(const float4*)(A + (size_t)grow * D + ko + v);
            *(float4*)&sA[r][v] = t;
        }
        // load W tile: 16 rows x 128 cols, two float4 per thread
        #pragma unroll
        for (int q = 0; q < 2; q++) {
            int e4 = tid + q * 256;          // 0..511
            int wr = e4 >> 5;                // k within chunk
            int wc = (e4 & 31) * 4;
            *(float4*)&sW[wr][wc] = *(const float4*)(W + (size_t)(ko + wr) * D + wc);
        }
        __syncthreads();
        #pragma unroll
        for (int k = 0; k < 16; k++) {
            float a[4], b[8];
            #pragma unroll
            for (int i = 0; i < 4; i++) a[i] = sA[ty + 16 * i][k];
            #pragma unroll
            for (int j = 0; j < 8; j++) b[j] = sW[k][tx + 16 * j];
            #pragma unroll
            for (int i = 0; i < 4; i++)
                #pragma unroll
                for (int j = 0; j < 8; j++)
                    acc[i][j] = fmaf(a[i], b[j], acc[i][j]);
        }
        __syncthreads();
    }

    if (MODE == 0) {
        #pragma unroll
        for (int i = 0; i < 4; i++) {
            int r = row0 + ty + 16 * i;
            if (r < N_NODES) {
                #pragma unroll
                for (int j = 0; j < 8; j++) {
                    int c = tx + 16 * j;
                    float v = acc[i][j] + bias[c];
                    g_bufB[(size_t)r * D + c] = fmaxf(v, 0.f);
                }
            }
        }
    } else {
        // stage tile + idx in smem, then segment-reduce over sorted idx
        #pragma unroll
        for (int i = 0; i < 4; i++) {
            int rloc = ty + 16 * i;
            #pragma unroll
            for (int j = 0; j < 8; j++) {
                int c = tx + 16 * j;
                sOut[rloc * D + c] = acc[i][j] + bias[c];
            }
        }
        if (tid < 64) {
            int r = row0 + tid;
            sIdx[tid] = (r < N_NODES) ? idx[r] : -1;
        }
        __syncthreads();
        int c    = tid & 127;
        int half = tid >> 7;          // rows [0,32) or [32,64)
        int rs = half * 32, re = rs + 32;
        float accp = 0.f;
        int cur = -1;
        for (int r = rs; r < re; r++) {
            int g = sIdx[r];
            if (g != cur) {
                if (cur >= 0) atomicAdd(&g_pooled[cur * D + c], accp);
                accp = 0.f;
                cur = g;
            }
            if (g >= 0) accp += sOut[r * D + c];
        }
        if (cur >= 0) atomicAdd(&g_pooled[cur * D + c], accp);
    }
}

// ---------------------------------------------------------------------------
// BatchNorm stats over the 512 graphs (two-pass for accuracy)
// ---------------------------------------------------------------------------
__global__ void bn_stats(const float* __restrict__ gamma,
                         const float* __restrict__ beta) {
    int c = threadIdx.x;            // 128 threads
    float s = 0.f;
    #pragma unroll 8
    for (int r = 0; r < N_GRAPHS; r++) s += g_pooled[r * D + c];
    float mean = s * (1.f / N_GRAPHS);
    float ss = 0.f;
    #pragma unroll 8
    for (int r = 0; r < N_GRAPHS; r++) {
        float d = g_pooled[r * D + c] - mean;
        ss += d * d;
    }
    float var = ss * (1.f / N_GRAPHS);
    float sc = rsqrtf(var + BN_EPS) * gamma[c];
    g_scale[c] = sc;
    g_shift[c] = beta[c] - mean * sc;
}

// ---------------------------------------------------------------------------
// Head: BN-apply, relu(@W3+b3), @W4+b4, log_softmax. One block per graph.
// ---------------------------------------------------------------------------
__global__ void head(const float* __restrict__ W3, const float* __restrict__ b3,
                     const float* __restrict__ W4, const float* __restrict__ b4,
                     float* __restrict__ out) {
    int g = blockIdx.x;
    int c = threadIdx.x;            // 128 threads
    __shared__ float sNb[D];
    __shared__ float sZg[D];
    __shared__ float sL[N_CLASS];
    __shared__ float sLse;

    float p = g_pooled[g * D + c];
    sNb[c] = p * g_scale[c] + g_shift[c];
    __syncthreads();

    float acc = b3[c];
    #pragma unroll 8
    for (int k = 0; k < D; k++) acc = fmaf(sNb[k], W3[(size_t)k * D + c], acc);
    sZg[c] = fmaxf(acc, 0.f);
    __syncthreads();

    if (c < N_CLASS) {
        float l = b4[c];
        #pragma unroll 8
        for (int k = 0; k < D; k++) l = fmaf(sZg[k], W4[(size_t)k * N_CLASS + c], l);
        sL[c] = l;
    }
    __syncthreads();

    if (c == 0) {
        float m = sL[0];
        #pragma unroll
        for (int i = 1; i < N_CLASS; i++) m = fmaxf(m, sL[i]);
        float se = 0.f;
        #pragma unroll
        for (int i = 0; i < N_CLASS; i++) se += expf(sL[i] - m);
        sLse = m + logf(se);
    }
    __syncthreads();

    if (c < N_CLASS) out[g * N_CLASS + c] = sL[c] - sLse;
}

// ---------------------------------------------------------------------------
extern "C" void kernel_launch(void* const* d_in, const int* in_sizes, int n_in,
                              void* d_out, int out_size) {
    const float* x     = (const float*)d_in[0];
    const int*   ei    = (const int*)d_in[1];
    const int*   idx   = (const int*)d_in[2];
    const float* W1    = (const float*)d_in[3];
    const float* b1    = (const float*)d_in[4];
    const float* W2    = (const float*)d_in[5];
    const float* b2    = (const float*)d_in[6];
    const float* W3    = (const float*)d_in[7];
    const float* b3    = (const float*)d_in[8];
    const float* W4    = (const float*)d_in[9];
    const float* b4    = (const float*)d_in[10];
    const float* gamma = (const float*)d_in[11];
    const float* beta  = (const float*)d_in[12];
    float* out = (float*)d_out;

    const int* src = ei;             // edge_index[0]
    const int* dst = ei + N_EDGES;   // edge_index[1]

    const int initBlocks = (int)((NT4 + 255) / 256);
    const int edgeBlocks = N_EDGES / 8;            // 8 edges/block (256 thr)
    const int gemmBlocks = (N_NODES + 63) / 64;    // 1563

    zero_pooled<<<(N_GRAPHS * D + 255) / 256, 256>>>();

    // layer 1: agg1 = x + scatter(x[src]->dst); z1 = relu(agg1 @ W1 + b1)
    init_agg_ext<<<initBlocks, 256>>>((const float4*)x);
    edge_agg<0><<<edgeBlocks, 256>>>(x, src, dst);
    gemm128<0><<<gemmBlocks, 256>>>(W1, b1, nullptr);

    // layer 2: agg2 = z1 + scatter(z1[src]->dst); h = agg2 @ W2 + b2; pool
    init_agg_fromB<<<initBlocks, 256>>>();
    edge_agg<1><<<edgeBlocks, 256>>>(nullptr, src, dst);
    gemm128<1><<<gemmBlocks, 256>>>(W2, b2, idx);

    // head
    bn_stats<<<1, 128>>>(gamma, beta);
    head<<<N_GRAPHS, 128>>>(W3, b3, W4, b4, out);
}

// round 5
// speedup vs baseline: 1.6314x; 1.6314x over previous
#include <cuda_runtime.h>
#include <math.h>

#define N_NODES  100000
#define N_EDGES  1600000
#define D        128
#define N_GRAPHS 512
#define N_CLASS  10
#define BN_EPS   1e-5f

#define NT   ((size_t)N_NODES * D)      // 12.8M floats
#define NT4  (NT / 4)                   // 3.2M float4

// Scratch (allocation-free: __device__ globals)
__device__ float g_bufA[NT];            // agg1, then agg2
__device__ float g_bufB[NT];            // z1
__device__ float g_pooled[N_GRAPHS * D];
__device__ float g_scale[D];
__device__ float g_shift[D];

// ---------------------------------------------------------------------------
// init: g_bufA = src (self-loop term of aggregation)
// ---------------------------------------------------------------------------
__global__ void init_agg_ext(const float4* __restrict__ src4) {
    size_t i = (size_t)blockIdx.x * blockDim.x + threadIdx.x;
    if (i < NT4) ((float4*)g_bufA)[i] = src4[i];
}
__global__ void init_agg_fromB() {
    size_t i = (size_t)blockIdx.x * blockDim.x + threadIdx.x;
    if (i < NT4) ((float4*)g_bufA)[i] = ((const float4*)g_bufB)[i];
}
__global__ void zero_pooled() {
    int i = blockIdx.x * blockDim.x + threadIdx.x;
    if (i < N_GRAPHS * D) g_pooled[i] = 0.f;
}

// ---------------------------------------------------------------------------
// Edge scatter-add: g_bufA[dst] += h[src], one warp per edge (128 floats).
// One red.global.add.v4.f32 (16B) per lane instead of 4 scalar atomics.
// SRC==0: h = external pointer (x). SRC==1: h = g_bufB (z1).
// ---------------------------------------------------------------------------
__device__ __forceinline__ void red_add_v4(float* p, float4 v) {
    asm volatile("red.global.add.v4.f32 [%0], {%1, %2, %3, %4};"
                 :: "l"(p), "f"(v.x), "f"(v.y), "f"(v.z), "f"(v.w)
                 : "memory");
}

template<int SRC>
__global__ __launch_bounds__(512)
void edge_agg(const float* __restrict__ hext,
              const int* __restrict__ src,
              const int* __restrict__ dst) {
    int e = blockIdx.x * (blockDim.x >> 5) + (threadIdx.x >> 5);
    if (e >= N_EDGES) return;
    const float* h = (SRC == 0) ? hext : g_bufB;
    int lane = threadIdx.x & 31;
    int s = __ldg(src + e);
    int d = __ldg(dst + e);
    float4 v = __ldg(((const float4*)(h + (size_t)s * D)) + lane);
    red_add_v4(g_bufA + (size_t)d * D + lane * 4, v);
}

// ---------------------------------------------------------------------------
// GEMM: [M=100000,128] @ [128,128] + bias, tiled 64x128 per block, 256 thr.
// MODE 0: out = relu(.) -> g_bufB
// MODE 1: out (no relu) pooled by sorted idx -> atomicAdd g_pooled (few atomics
//         per block thanks to in-block segment reduction over sorted idx)
// ---------------------------------------------------------------------------
template<int MODE>
__global__ __launch_bounds__(256)
void gemm128(const float* __restrict__ W, const float* __restrict__ bias,
             const int* __restrict__ idx) {
    __shared__ float sA[64][16];
    __shared__ float sW[16][128];
    __shared__ float sOut[MODE == 1 ? 64 * 128 : 1];
    __shared__ int   sIdx[MODE == 1 ? 64 : 1];

    const float* A = g_bufA;
    int tid = threadIdx.x;
    int tx = tid & 15;          // N index base (cols tx + 16*j)
    int ty = tid >> 4;          // M index base (rows ty + 16*i)
    int row0 = blockIdx.x * 64;

    float acc[4][8];
    #pragma unroll
    for (int i = 0; i < 4; i++)
        #pragma unroll
        for (int j = 0; j < 8; j++) acc[i][j] = 0.f;

    for (int ko = 0; ko < D; ko += 16) {
        // load A tile: 64 rows x 16 cols, one float4 per thread
        {
            int r = tid >> 2;
            int v = (tid & 3) * 4;
            int grow = row0 + r;
            float4 t = make_float4(0.f, 0.f, 0.f, 0.f);
            if (grow < N_NODES)
                t = *(const float4*)(A + (size_t)grow * D + ko + v);
            *(float4*)&sA[r][v] = t;
        }
        // load W tile: 16 rows x 128 cols, two float4 per thread
        #pragma unroll
        for (int q = 0; q < 2; q++) {
            int e4 = tid + q * 256;          // 0..511
            int wr = e4 >> 5;                // k within chunk
            int wc = (e4 & 31) * 4;
            *(float4*)&sW[wr][wc] = *(const float4*)(W + (size_t)(ko + wr) * D + wc);
        }
        __syncthreads();
        #pragma unroll
        for (int k = 0; k < 16; k++) {
            float a[4], b[8];
            #pragma unroll
            for (int i = 0; i < 4; i++) a[i] = sA[ty + 16 * i][k];
            #pragma unroll
            for (int j = 0; j < 8; j++) b[j] = sW[k][tx + 16 * j];
            #pragma unroll
            for (int i = 0; i < 4; i++)
                #pragma unroll
                for (int j = 0; j < 8; j++)
                    acc[i][j] = fmaf(a[i], b[j], acc[i][j]);
        }
        __syncthreads();
    }

    if (MODE == 0) {
        #pragma unroll
        for (int i = 0; i < 4; i++) {
            int r = row0 + ty + 16 * i;
            if (r < N_NODES) {
                #pragma unroll
                for (int j = 0; j < 8; j++) {
                    int c = tx + 16 * j;
                    float v = acc[i][j] + bias[c];
                    g_bufB[(size_t)r * D + c] = fmaxf(v, 0.f);
                }
            }
        }
    } else {
        // stage tile + idx in smem, then segment-reduce over sorted idx
        #pragma unroll
        for (int i = 0; i < 4; i++) {
            int rloc = ty + 16 * i;
            #pragma unroll
            for (int j = 0; j < 8; j++) {
                int c = tx + 16 * j;
                sOut[rloc * D + c] = acc[i][j] + bias[c];
            }
        }
        if (tid < 64) {
            int r = row0 + tid;
            sIdx[tid] = (r < N_NODES) ? idx[r] : -1;
        }
        __syncthreads();
        int c    = tid & 127;
        int half = tid >> 7;          // rows [0,32) or [32,64)
        int rs = half * 32, re = rs + 32;
        float accp = 0.f;
        int cur = -1;
        for (int r = rs; r < re; r++) {
            int g = sIdx[r];
            if (g != cur) {
                if (cur >= 0) atomicAdd(&g_pooled[cur * D + c], accp);
                accp = 0.f;
                cur = g;
            }
            if (g >= 0) accp += sOut[r * D + c];
        }
        if (cur >= 0) atomicAdd(&g_pooled[cur * D + c], accp);
    }
}

// ---------------------------------------------------------------------------
// BatchNorm stats over the 512 graphs (two-pass for accuracy)
// ---------------------------------------------------------------------------
__global__ void bn_stats(const float* __restrict__ gamma,
                         const float* __restrict__ beta) {
    int c = threadIdx.x;            // 128 threads
    float s = 0.f;
    #pragma unroll 8
    for (int r = 0; r < N_GRAPHS; r++) s += g_pooled[r * D + c];
    float mean = s * (1.f / N_GRAPHS);
    float ss = 0.f;
    #pragma unroll 8
    for (int r = 0; r < N_GRAPHS; r++) {
        float d = g_pooled[r * D + c] - mean;
        ss += d * d;
    }
    float var = ss * (1.f / N_GRAPHS);
    float sc = rsqrtf(var + BN_EPS) * gamma[c];
    g_scale[c] = sc;
    g_shift[c] = beta[c] - mean * sc;
}

// ---------------------------------------------------------------------------
// Head: BN-apply, relu(@W3+b3), @W4+b4, log_softmax. One block per graph.
// ---------------------------------------------------------------------------
__global__ void head(const float* __restrict__ W3, const float* __restrict__ b3,
                     const float* __restrict__ W4, const float* __restrict__ b4,
                     float* __restrict__ out) {
    int g = blockIdx.x;
    int c = threadIdx.x;            // 128 threads
    __shared__ float sNb[D];
    __shared__ float sZg[D];
    __shared__ float sL[N_CLASS];
    __shared__ float sLse;

    float p = g_pooled[g * D + c];
    sNb[c] = p * g_scale[c] + g_shift[c];
    __syncthreads();

    float acc = b3[c];
    #pragma unroll 8
    for (int k = 0; k < D; k++) acc = fmaf(sNb[k], W3[(size_t)k * D + c], acc);
    sZg[c] = fmaxf(acc, 0.f);
    __syncthreads();

    if (c < N_CLASS) {
        float l = b4[c];
        #pragma unroll 8
        for (int k = 0; k < D; k++) l = fmaf(sZg[k], W4[(size_t)k * N_CLASS + c], l);
        sL[c] = l;
    }
    __syncthreads();

    if (c == 0) {
        float m = sL[0];
        #pragma unroll
        for (int i = 1; i < N_CLASS; i++) m = fmaxf(m, sL[i]);
        float se = 0.f;
        #pragma unroll
        for (int i = 0; i < N_CLASS; i++) se += expf(sL[i] - m);
        sLse = m + logf(se);
    }
    __syncthreads();

    if (c < N_CLASS) out[g * N_CLASS + c] = sL[c] - sLse;
}

// ---------------------------------------------------------------------------
extern "C" void kernel_launch(void* const* d_in, const int* in_sizes, int n_in,
                              void* d_out, int out_size) {
    const float* x     = (const float*)d_in[0];
    const int*   ei    = (const int*)d_in[1];
    const int*   idx   = (const int*)d_in[2];
    const float* W1    = (const float*)d_in[3];
    const float* b1    = (const float*)d_in[4];
    const float* W2    = (const float*)d_in[5];
    const float* b2    = (const float*)d_in[6];
    const float* W3    = (const float*)d_in[7];
    const float* b3    = (const float*)d_in[8];
    const float* W4    = (const float*)d_in[9];
    const float* b4    = (const float*)d_in[10];
    const float* gamma = (const float*)d_in[11];
    const float* beta  = (const float*)d_in[12];
    float* out = (float*)d_out;

    const int* src = ei;             // edge_index[0]
    const int* dst = ei + N_EDGES;   // edge_index[1]

    const int initBlocks = (int)((NT4 + 255) / 256);
    const int edgeBlocks = N_EDGES / 16;           // 16 edges/block (512 thr)
    const int gemmBlocks = (N_NODES + 63) / 64;    // 1563

    zero_pooled<<<(N_GRAPHS * D + 255) / 256, 256>>>();

    // layer 1: agg1 = x + scatter(x[src]->dst); z1 = relu(agg1 @ W1 + b1)
    init_agg_ext<<<initBlocks, 256>>>((const float4*)x);
    edge_agg<0><<<edgeBlocks, 512>>>(x, src, dst);
    gemm128<0><<<gemmBlocks, 256>>>(W1, b1, nullptr);

    // layer 2: agg2 = z1 + scatter(z1[src]->dst); h = agg2 @ W2 + b2; pool
    init_agg_fromB<<<initBlocks, 256>>>();
    edge_agg<1><<<edgeBlocks, 512>>>(nullptr, src, dst);
    gemm128<1><<<gemmBlocks, 256>>>(W2, b2, idx);

    // head
    bn_stats<<<1, 128>>>(gamma, beta);
    head<<<N_GRAPHS, 128>>>(W3, b3, W4, b4, out);
}

// round 6
// speedup vs baseline: 2.9173x; 1.7883x over previous
#include <cuda_runtime.h>
#include <math.h>

#define N_NODES  100000
#define N_EDGES  1600000
#define D        128
#define N_GRAPHS 512
#define N_CLASS  10
#define BN_EPS   1e-5f

#define NT   ((size_t)N_NODES * D)      // 12.8M floats

#define SCAN_BLK 512
#define NSCAN    ((N_NODES + SCAN_BLK - 1) / SCAN_BLK)   // 196

// Scratch (allocation-free: __device__ globals)
__device__ float g_bufA[NT];            // agg1, then agg2
__device__ float g_bufB[NT];            // z1
__device__ float g_pooled[N_GRAPHS * D];
__device__ float g_scale[D];
__device__ float g_shift[D];

// CSR build scratch
__device__ int g_deg[N_NODES];
__device__ int g_scan[N_NODES];         // inclusive scan within scan-block
__device__ int g_bsum[NSCAN];
__device__ int g_boff[NSCAN];
__device__ int g_rowstart[N_NODES];
__device__ int g_cursor[N_NODES];
__device__ int g_csrsrc[N_EDGES];

// ---------------------------------------------------------------------------
// CSR build
// ---------------------------------------------------------------------------
__global__ void zero_misc() {
    int i = blockIdx.x * blockDim.x + threadIdx.x;
    if (i < N_NODES) g_deg[i] = 0;
    if (i < N_GRAPHS * D) g_pooled[i] = 0.f;
}

__global__ void hist_deg(const int* __restrict__ dst) {
    int e = blockIdx.x * blockDim.x + threadIdx.x;
    if (e < N_EDGES) atomicAdd(&g_deg[dst[e]], 1);
}

__global__ __launch_bounds__(SCAN_BLK) void scan_l1() {
    __shared__ int s[SCAN_BLK];
    int t = threadIdx.x;
    int i = blockIdx.x * SCAN_BLK + t;
    int v = (i < N_NODES) ? g_deg[i] : 0;
    s[t] = v;
    __syncthreads();
    #pragma unroll
    for (int off = 1; off < SCAN_BLK; off <<= 1) {
        int add = (t >= off) ? s[t - off] : 0;
        __syncthreads();
        s[t] += add;
        __syncthreads();
    }
    if (i < N_NODES) g_scan[i] = s[t];
    if (t == SCAN_BLK - 1) g_bsum[blockIdx.x] = s[t];
}

__global__ __launch_bounds__(256) void scan_l2() {
    __shared__ int s[256];
    int t = threadIdx.x;
    int v = (t < NSCAN) ? g_bsum[t] : 0;
    s[t] = v;
    __syncthreads();
    #pragma unroll
    for (int off = 1; off < 256; off <<= 1) {
        int add = (t >= off) ? s[t - off] : 0;
        __syncthreads();
        s[t] += add;
        __syncthreads();
    }
    if (t < NSCAN) g_boff[t] = s[t] - v;   // exclusive offsets
}

__global__ void scan_l3() {
    int i = blockIdx.x * blockDim.x + threadIdx.x;
    if (i < N_NODES) {
        int rs = g_scan[i] - g_deg[i] + g_boff[i / SCAN_BLK];  // exclusive
        g_rowstart[i] = rs;
        g_cursor[i] = rs;
    }
}

__global__ void scatter_csr(const int* __restrict__ src,
                            const int* __restrict__ dst) {
    int e = blockIdx.x * blockDim.x + threadIdx.x;
    if (e < N_EDGES) {
        int pos = atomicAdd(&g_cursor[dst[e]], 1);
        g_csrsrc[pos] = src[e];
    }
}

// ---------------------------------------------------------------------------
// Gather-based aggregation: g_bufA[n] = h[n] + sum_{s in N(n)} h[s]
// One warp per node; no float atomics, self-loop folded in.
// SRC==0: h = external (x). SRC==1: h = g_bufB (z1).
// ---------------------------------------------------------------------------
template<int SRC>
__global__ __launch_bounds__(256)
void node_agg(const float* __restrict__ hext) {
    int n = blockIdx.x * 8 + (threadIdx.x >> 5);
    if (n >= N_NODES) return;
    int lane = threadIdx.x & 31;
    const float4* h4 = (const float4*)((SRC == 0) ? hext : (const float*)g_bufB);

    float4 acc  = __ldg(h4 + (size_t)n * 32 + lane);   // self loop
    float4 acc2 = make_float4(0.f, 0.f, 0.f, 0.f);

    int s0 = g_rowstart[n];
    int e0 = s0 + g_deg[n];
    for (int base = s0; base < e0; base += 32) {
        int cnt = min(32, e0 - base);
        int sv = (lane < cnt) ? __ldg(g_csrsrc + base + lane) : 0;
        int j = 0;
        for (; j + 1 < cnt; j += 2) {
            int sa = __shfl_sync(0xffffffffu, sv, j);
            int sb = __shfl_sync(0xffffffffu, sv, j + 1);
            float4 va = __ldg(h4 + (size_t)sa * 32 + lane);
            float4 vb = __ldg(h4 + (size_t)sb * 32 + lane);
            acc.x += va.x;  acc.y += va.y;  acc.z += va.z;  acc.w += va.w;
            acc2.x += vb.x; acc2.y += vb.y; acc2.z += vb.z; acc2.w += vb.w;
        }
        if (j < cnt) {
            int sa = __shfl_sync(0xffffffffu, sv, j);
            float4 va = __ldg(h4 + (size_t)sa * 32 + lane);
            acc.x += va.x; acc.y += va.y; acc.z += va.z; acc.w += va.w;
        }
    }
    acc.x += acc2.x; acc.y += acc2.y; acc.z += acc2.z; acc.w += acc2.w;
    ((float4*)g_bufA)[(size_t)n * 32 + lane] = acc;
}

// ---------------------------------------------------------------------------
// GEMM: [M=100000,128] @ [128,128] + bias, tiled 64x128 per block, 256 thr.
// Thread tile 4x8: rows ty+16*i, cols {tx*4..tx*4+3, 64+tx*4..}. B-reads are
// two LDS.128 per k (6 LDS vs 12 before -> fewer issue slots, fma-bound).
// MODE 0: relu -> g_bufB.  MODE 1: +bias, segment-pool by sorted idx.
// ---------------------------------------------------------------------------
template<int MODE>
__global__ __launch_bounds__(256)
void gemm128(const float* __restrict__ W, const float* __restrict__ bias,
             const int* __restrict__ idx) {
    __shared__ float sA[64][16];
    __shared__ float sW[16][128];
    __shared__ float sOut[MODE == 1 ? 64 * 128 : 1];
    __shared__ int   sIdx[MODE == 1 ? 64 : 1];

    const float* A = g_bufA;
    int tid = threadIdx.x;
    int tx = tid & 15;          // col base: tx*4 and 64+tx*4
    int ty = tid >> 4;          // row base: ty + 16*i
    int row0 = blockIdx.x * 64;

    float4 bb0 = __ldg((const float4*)(bias) + tx);        // cols tx*4..+3
    float4 bb1 = __ldg((const float4*)(bias + 64) + tx);   // cols 64+tx*4..+3

    float acc[4][8];
    #pragma unroll
    for (int i = 0; i < 4; i++)
        #pragma unroll
        for (int j = 0; j < 8; j++) acc[i][j] = 0.f;

    for (int ko = 0; ko < D; ko += 16) {
        // A tile: 64 rows x 16 cols, one float4 per thread
        {
            int r = tid >> 2;
            int v = (tid & 3) * 4;
            int grow = row0 + r;
            float4 t = make_float4(0.f, 0.f, 0.f, 0.f);
            if (grow < N_NODES)
                t = *(const float4*)(A + (size_t)grow * D + ko + v);
            *(float4*)&sA[r][v] = t;
        }
        // W tile: 16 rows x 128 cols, two float4 per thread
        #pragma unroll
        for (int q = 0; q < 2; q++) {
            int e4 = tid + q * 256;
            int wr = e4 >> 5;
            int wc = (e4 & 31) * 4;
            *(float4*)&sW[wr][wc] = *(const float4*)(W + (size_t)(ko + wr) * D + wc);
        }
        __syncthreads();
        #pragma unroll
        for (int k = 0; k < 16; k++) {
            float a[4];
            #pragma unroll
            for (int i = 0; i < 4; i++) a[i] = sA[ty + 16 * i][k];
            float4 b0 = *(const float4*)&sW[k][tx * 4];
            float4 b1 = *(const float4*)&sW[k][64 + tx * 4];
            #pragma unroll
            for (int i = 0; i < 4; i++) {
                acc[i][0] = fmaf(a[i], b0.x, acc[i][0]);
                acc[i][1] = fmaf(a[i], b0.y, acc[i][1]);
                acc[i][2] = fmaf(a[i], b0.z, acc[i][2]);
                acc[i][3] = fmaf(a[i], b0.w, acc[i][3]);
                acc[i][4] = fmaf(a[i], b1.x, acc[i][4]);
                acc[i][5] = fmaf(a[i], b1.y, acc[i][5]);
                acc[i][6] = fmaf(a[i], b1.z, acc[i][6]);
                acc[i][7] = fmaf(a[i], b1.w, acc[i][7]);
            }
        }
        __syncthreads();
    }

    if (MODE == 0) {
        #pragma unroll
        for (int i = 0; i < 4; i++) {
            int r = row0 + ty + 16 * i;
            if (r < N_NODES) {
                float4 v0, v1;
                v0.x = fmaxf(acc[i][0] + bb0.x, 0.f);
                v0.y = fmaxf(acc[i][1] + bb0.y, 0.f);
                v0.z = fmaxf(acc[i][2] + bb0.z, 0.f);
                v0.w = fmaxf(acc[i][3] + bb0.w, 0.f);
                v1.x = fmaxf(acc[i][4] + bb1.x, 0.f);
                v1.y = fmaxf(acc[i][5] + bb1.y, 0.f);
                v1.z = fmaxf(acc[i][6] + bb1.z, 0.f);
                v1.w = fmaxf(acc[i][7] + bb1.w, 0.f);
                *(float4*)(g_bufB + (size_t)r * D + tx * 4) = v0;
                *(float4*)(g_bufB + (size_t)r * D + 64 + tx * 4) = v1;
            }
        }
    } else {
        #pragma unroll
        for (int i = 0; i < 4; i++) {
            int rloc = ty + 16 * i;
            float4 v0, v1;
            v0.x = acc[i][0] + bb0.x;  v0.y = acc[i][1] + bb0.y;
            v0.z = acc[i][2] + bb0.z;  v0.w = acc[i][3] + bb0.w;
            v1.x = acc[i][4] + bb1.x;  v1.y = acc[i][5] + bb1.y;
            v1.z = acc[i][6] + bb1.z;  v1.w = acc[i][7] + bb1.w;
            *(float4*)&sOut[rloc * D + tx * 4] = v0;
            *(float4*)&sOut[rloc * D + 64 + tx * 4] = v1;
        }
        if (tid < 64) {
            int r = row0 + tid;
            sIdx[tid] = (r < N_NODES) ? idx[r] : -1;
        }
        __syncthreads();
        int c    = tid & 127;
        int half = tid >> 7;
        int rs = half * 32, re = rs + 32;
        float accp = 0.f;
        int cur = -1;
        for (int r = rs; r < re; r++) {
            int g = sIdx[r];
            if (g != cur) {
                if (cur >= 0) atomicAdd(&g_pooled[cur * D + c], accp);
                accp = 0.f;
                cur = g;
            }
            if (g >= 0) accp += sOut[r * D + c];
        }
        if (cur >= 0) atomicAdd(&g_pooled[cur * D + c], accp);
    }
}

// ---------------------------------------------------------------------------
// BatchNorm stats over the 512 graphs (two-pass)
// ---------------------------------------------------------------------------
__global__ void bn_stats(const float* __restrict__ gamma,
                         const float* __restrict__ beta) {
    int c = threadIdx.x;            // 128 threads
    float s = 0.f;
    #pragma unroll 8
    for (int r = 0; r < N_GRAPHS; r++) s += g_pooled[r * D + c];
    float mean = s * (1.f / N_GRAPHS);
    float ss = 0.f;
    #pragma unroll 8
    for (int r = 0; r < N_GRAPHS; r++) {
        float d = g_pooled[r * D + c] - mean;
        ss += d * d;
    }
    float var = ss * (1.f / N_GRAPHS);
    float sc = rsqrtf(var + BN_EPS) * gamma[c];
    g_scale[c] = sc;
    g_shift[c] = beta[c] - mean * sc;
}

// ---------------------------------------------------------------------------
// Head: BN-apply, relu(@W3+b3), @W4+b4, log_softmax. One block per graph.
// ---------------------------------------------------------------------------
__global__ void head(const float* __restrict__ W3, const float* __restrict__ b3,
                     const float* __restrict__ W4, const float* __restrict__ b4,
                     float* __restrict__ out) {
    int g = blockIdx.x;
    int c = threadIdx.x;            // 128 threads
    __shared__ float sNb[D];
    __shared__ float sZg[D];
    __shared__ float sL[N_CLASS];
    __shared__ float sLse;

    float p = g_pooled[g * D + c];
    sNb[c] = p * g_scale[c] + g_shift[c];
    __syncthreads();

    float acc = b3[c];
    #pragma unroll 8
    for (int k = 0; k < D; k++) acc = fmaf(sNb[k], W3[(size_t)k * D + c], acc);
    sZg[c] = fmaxf(acc, 0.f);
    __syncthreads();

    if (c < N_CLASS) {
        float l = b4[c];
        #pragma unroll 8
        for (int k = 0; k < D; k++) l = fmaf(sZg[k], W4[(size_t)k * N_CLASS + c], l);
        sL[c] = l;
    }
    __syncthreads();

    if (c == 0) {
        float m = sL[0];
        #pragma unroll
        for (int i = 1; i < N_CLASS; i++) m = fmaxf(m, sL[i]);
        float se = 0.f;
        #pragma unroll
        for (int i = 0; i < N_CLASS; i++) se += expf(sL[i] - m);
        sLse = m + logf(se);
    }
    __syncthreads();

    if (c < N_CLASS) out[g * N_CLASS + c] = sL[c] - sLse;
}

// ---------------------------------------------------------------------------
extern "C" void kernel_launch(void* const* d_in, const int* in_sizes, int n_in,
                              void* d_out, int out_size) {
    const float* x     = (const float*)d_in[0];
    const int*   ei    = (const int*)d_in[1];
    const int*   idx   = (const int*)d_in[2];
    const float* W1    = (const float*)d_in[3];
    const float* b1    = (const float*)d_in[4];
    const float* W2    = (const float*)d_in[5];
    const float* b2    = (const float*)d_in[6];
    const float* W3    = (const float*)d_in[7];
    const float* b3    = (const float*)d_in[8];
    const float* W4    = (const float*)d_in[9];
    const float* b4    = (const float*)d_in[10];
    const float* gamma = (const float*)d_in[11];
    const float* beta  = (const float*)d_in[12];
    float* out = (float*)d_out;

    const int* src = ei;             // edge_index[0]
    const int* dst = ei + N_EDGES;   // edge_index[1]

    const int gemmBlocks = (N_NODES + 63) / 64;     // 1563
    const int aggBlocks  = (N_NODES + 7) / 8;       // 12500 (8 warps/block)
    const int eBlocks    = (N_EDGES + 511) / 512;

    // CSR build (once, serves both agg passes)
    zero_misc<<<(N_NODES + 255) / 256, 256>>>();
    hist_deg<<<eBlocks, 512>>>(dst);
    scan_l1<<<NSCAN, SCAN_BLK>>>();
    scan_l2<<<1, 256>>>();
    scan_l3<<<(N_NODES + 255) / 256, 256>>>();
    scatter_csr<<<eBlocks, 512>>>(src, dst);

    // layer 1: agg1 = x + gather; z1 = relu(agg1 @ W1 + b1)
    node_agg<0><<<aggBlocks, 256>>>(x);
    gemm128<0><<<gemmBlocks, 256>>>(W1, b1, nullptr);

    // layer 2: agg2 = z1 + gather; h = agg2 @ W2 + b2; pool
    node_agg<1><<<aggBlocks, 256>>>(nullptr);
    gemm128<1><<<gemmBlocks, 256>>>(W2, b2, idx);

    // head
    bn_stats<<<1, 128>>>(gamma, beta);
    head<<<N_GRAPHS, 128>>>(W3, b3, W4, b4, out);
}

// round 8
// speedup vs baseline: 3.3039x; 1.1325x over previous
#include <cuda_runtime.h>
#include <cuda_bf16.h>
#include <math.h>
#include <stdint.h>

#define N_NODES  100000
#define N_EDGES  1600000
#define D        128
#define N_GRAPHS 512
#define N_CLASS  10
#define BN_EPS   1e-5f

#define NT   ((size_t)N_NODES * D)      // 12.8M floats

#define SCAN_BLK 512
#define NSCAN    ((N_NODES + SCAN_BLK - 1) / SCAN_BLK)   // 196

// ---------------------------------------------------------------------------
// Scratch (allocation-free: __device__ globals)
// ---------------------------------------------------------------------------
__device__ float g_bufA[NT];            // agg1, then agg2
__device__ float g_bufB[NT];            // z1
__device__ float g_pooled[N_GRAPHS * D];
__device__ float g_scale[D];
__device__ float g_shift[D];

__device__ int g_deg[N_NODES];
__device__ int g_scan[N_NODES];
__device__ int g_bsum[NSCAN];
__device__ int g_boff[NSCAN];
__device__ int g_rowstart[N_NODES];
__device__ int g_cursor[N_NODES];
__device__ int g_csrsrc[N_EDGES];

// W split into bf16 hi/lo, n-major ([n][k]) — B operand for mma row.col
__device__ __nv_bfloat16 g_Whi[2][D * D];
__device__ __nv_bfloat16 g_Wlo[2][D * D];

// ---------------------------------------------------------------------------
// helpers
// ---------------------------------------------------------------------------
__device__ __forceinline__ uint32_t smem_to_u32(const void* p) {
    uint32_t a;
    asm("{ .reg .u64 t; cvta.to.shared.u64 t, %1; cvt.u32.u64 %0, t; }"
        : "=r"(a) : "l"(p));
    return a;
}

__device__ __forceinline__ void ldm_x4(uint32_t* r, uint32_t addr) {
    asm volatile("ldmatrix.sync.aligned.m8n8.x4.shared.b16 {%0,%1,%2,%3}, [%4];"
                 : "=r"(r[0]), "=r"(r[1]), "=r"(r[2]), "=r"(r[3]) : "r"(addr));
}

__device__ __forceinline__ void mma_bf16(float* c, const uint32_t* a,
                                         const uint32_t* b) {
    asm volatile(
        "mma.sync.aligned.m16n8k16.row.col.f32.bf16.bf16.f32 "
        "{%0,%1,%2,%3}, {%4,%5,%6,%7}, {%8,%9}, {%0,%1,%2,%3};"
        : "+f"(c[0]), "+f"(c[1]), "+f"(c[2]), "+f"(c[3])
        : "r"(a[0]), "r"(a[1]), "r"(a[2]), "r"(a[3]), "r"(b[0]), "r"(b[1]));
}

__device__ __forceinline__ uint32_t pkbf2(float a, float b) {
    __nv_bfloat162 t = __floats2bfloat162_rn(a, b);
    return *reinterpret_cast<uint32_t*>(&t);
}

// ---------------------------------------------------------------------------
// CSR build
// ---------------------------------------------------------------------------
__global__ void zero_misc() {
    int i = blockIdx.x * blockDim.x + threadIdx.x;
    if (i < N_NODES) g_deg[i] = 0;
    if (i < N_GRAPHS * D) g_pooled[i] = 0.f;
}
__global__ void hist_deg(const int* __restrict__ dst) {
    int e = blockIdx.x * blockDim.x + threadIdx.x;
    if (e < N_EDGES) atomicAdd(&g_deg[dst[e]], 1);
}
__global__ __launch_bounds__(SCAN_BLK) void scan_l1() {
    __shared__ int s[SCAN_BLK];
    int t = threadIdx.x;
    int i = blockIdx.x * SCAN_BLK + t;
    int v = (i < N_NODES) ? g_deg[i] : 0;
    s[t] = v;
    __syncthreads();
    #pragma unroll
    for (int off = 1; off < SCAN_BLK; off <<= 1) {
        int add = (t >= off) ? s[t - off] : 0;
        __syncthreads();
        s[t] += add;
        __syncthreads();
    }
    if (i < N_NODES) g_scan[i] = s[t];
    if (t == SCAN_BLK - 1) g_bsum[blockIdx.x] = s[t];
}
__global__ __launch_bounds__(256) void scan_l2() {
    __shared__ int s[256];
    int t = threadIdx.x;
    int v = (t < NSCAN) ? g_bsum[t] : 0;
    s[t] = v;
    __syncthreads();
    #pragma unroll
    for (int off = 1; off < 256; off <<= 1) {
        int add = (t >= off) ? s[t - off] : 0;
        __syncthreads();
        s[t] += add;
        __syncthreads();
    }
    if (t < NSCAN) g_boff[t] = s[t] - v;
}
__global__ void scan_l3() {
    int i = blockIdx.x * blockDim.x + threadIdx.x;
    if (i < N_NODES) {
        int rs = g_scan[i] - g_deg[i] + g_boff[i / SCAN_BLK];
        g_rowstart[i] = rs;
        g_cursor[i] = rs;
    }
}
__global__ void scatter_csr(const int* __restrict__ src,
                            const int* __restrict__ dst) {
    int e = blockIdx.x * blockDim.x + threadIdx.x;
    if (e < N_EDGES) {
        int pos = atomicAdd(&g_cursor[dst[e]], 1);
        g_csrsrc[pos] = src[e];
    }
}

// ---------------------------------------------------------------------------
// W split: g_Whi/g_Wlo[layer][n][k] = bf16 hi/lo of W[k][n]
// ---------------------------------------------------------------------------
__global__ void wprep(const float* __restrict__ W1, const float* __restrict__ W2) {
    int i = blockIdx.x * blockDim.x + threadIdx.x;
    if (i >= 2 * D * D) return;
    int layer = i >> 14;
    int k = (i >> 7) & 127;
    int n = i & 127;
    float v = (layer ? W2 : W1)[k * D + n];
    __nv_bfloat16 hi = __float2bfloat16_rn(v);
    float lo = v - __bfloat162float(hi);
    g_Whi[layer][n * D + k] = hi;
    g_Wlo[layer][n * D + k] = __float2bfloat16_rn(lo);
}

// ---------------------------------------------------------------------------
// Gather-based aggregation: g_bufA[n] = h[n] + sum_{s in N(n)} h[s]
// ---------------------------------------------------------------------------
template<int SRC>
__global__ __launch_bounds__(256)
void node_agg(const float* __restrict__ hext) {
    int n = blockIdx.x * 8 + (threadIdx.x >> 5);
    if (n >= N_NODES) return;
    int lane = threadIdx.x & 31;
    const float4* h4 = (const float4*)((SRC == 0) ? hext : (const float*)g_bufB);

    float4 acc  = __ldg(h4 + (size_t)n * 32 + lane);
    float4 acc2 = make_float4(0.f, 0.f, 0.f, 0.f);

    int s0 = g_rowstart[n];
    int e0 = s0 + g_deg[n];
    for (int base = s0; base < e0; base += 32) {
        int cnt = min(32, e0 - base);
        int sv = (lane < cnt) ? __ldg(g_csrsrc + base + lane) : 0;
        int j = 0;
        for (; j + 1 < cnt; j += 2) {
            int sa = __shfl_sync(0xffffffffu, sv, j);
            int sb = __shfl_sync(0xffffffffu, sv, j + 1);
            float4 va = __ldg(h4 + (size_t)sa * 32 + lane);
            float4 vb = __ldg(h4 + (size_t)sb * 32 + lane);
            acc.x += va.x;  acc.y += va.y;  acc.z += va.z;  acc.w += va.w;
            acc2.x += vb.x; acc2.y += vb.y; acc2.z += vb.z; acc2.w += vb.w;
        }
        if (j < cnt) {
            int sa = __shfl_sync(0xffffffffu, sv, j);
            float4 va = __ldg(h4 + (size_t)sa * 32 + lane);
            acc.x += va.x; acc.y += va.y; acc.z += va.z; acc.w += va.w;
        }
    }
    acc.x += acc2.x; acc.y += acc2.y; acc.z += acc2.z; acc.w += acc2.w;
    ((float4*)g_bufA)[(size_t)n * 32 + lane] = acc;
}

// ---------------------------------------------------------------------------
// Tensor-core GEMM via mma.sync (bf16 split-3, f32 accum).
// Block: 128 rows x 128 cols, 256 threads = 8 warps (4 m-groups x 2 n-groups),
// warp tile m32 x n64. SMEM tiles row stride 272B (conflict-free ldmatrix).
// MODE 0: relu(D + bias) -> g_bufB
// MODE 1: (D + bias) segment-pooled by sorted idx -> atomicAdd g_pooled
// ---------------------------------------------------------------------------
#define TSTRIDE 272                      // bytes per 128-bf16 row (+16B pad)
#define SM_AHI 0
#define SM_ALO 34816
#define SM_BHI 69632
#define SM_BLO 104448
#define SM_IDX 139264
#define SMEM_MMA (139264 + 512)

template<int MODE>
__global__ __launch_bounds__(256)
void gemm_mma(const __nv_bfloat16* __restrict__ Whi,
              const __nv_bfloat16* __restrict__ Wlo,
              const float* __restrict__ bias,
              const int* __restrict__ idx) {
    extern __shared__ __align__(16) char sbp[];
    uint32_t sb = smem_to_u32(sbp);

    int tid  = threadIdx.x;
    int wid  = tid >> 5;
    int lane = tid & 31;
    int row0 = blockIdx.x * 128;
    int mr = (wid >> 1) * 32;            // warp row base
    int nc = (wid & 1) * 64;             // warp col base

    // ---- stage A (fp32 -> bf16 hi/lo) ----
    {
        int row = tid >> 1;
        int kh  = (tid & 1) * 64;        // element offset
        int gr  = row0 + row;
        char* ahi = sbp + SM_AHI + row * TSTRIDE + kh * 2;
        char* alo = sbp + SM_ALO + row * TSTRIDE + kh * 2;
        if (gr < N_NODES) {
            const float4* Arow = (const float4*)(g_bufA + (size_t)gr * D + kh);
            #pragma unroll
            for (int g = 0; g < 8; g++) {
                float4 p = __ldg(Arow + 2 * g);
                float4 q = __ldg(Arow + 2 * g + 1);
                float f[8] = {p.x, p.y, p.z, p.w, q.x, q.y, q.z, q.w};
                float fh[8], fl[8];
                #pragma unroll
                for (int e = 0; e < 8; e++) {
                    __nv_bfloat16 h = __float2bfloat16_rn(f[e]);
                    fh[e] = __bfloat162float(h);
                    fl[e] = f[e] - fh[e];
                }
                uint4 hv, lv;
                hv.x = pkbf2(fh[0], fh[1]); hv.y = pkbf2(fh[2], fh[3]);
                hv.z = pkbf2(fh[4], fh[5]); hv.w = pkbf2(fh[6], fh[7]);
                lv.x = pkbf2(fl[0], fl[1]); lv.y = pkbf2(fl[2], fl[3]);
                lv.z = pkbf2(fl[4], fl[5]); lv.w = pkbf2(fl[6], fl[7]);
                *(uint4*)(ahi + 16 * g) = hv;
                *(uint4*)(alo + 16 * g) = lv;
            }
        } else {
            uint4 z = make_uint4(0, 0, 0, 0);
            #pragma unroll
            for (int g = 0; g < 8; g++) {
                *(uint4*)(ahi + 16 * g) = z;
                *(uint4*)(alo + 16 * g) = z;
            }
        }
    }
    // ---- stage B (precomputed bf16 hi/lo, n-major) ----
    {
        int n  = tid >> 1;
        int kh = (tid & 1) * 64;
        const uint4* ph = (const uint4*)(Whi + n * D + kh);
        const uint4* pl = (const uint4*)(Wlo + n * D + kh);
        char* bhi = sbp + SM_BHI + n * TSTRIDE + kh * 2;
        char* blo = sbp + SM_BLO + n * TSTRIDE + kh * 2;
        #pragma unroll
        for (int g = 0; g < 8; g++) {
            *(uint4*)(bhi + 16 * g) = __ldg(ph + g);
            *(uint4*)(blo + 16 * g) = __ldg(pl + g);
        }
    }
    if (MODE == 1 && tid < 128) {
        int r = row0 + tid;
        ((int*)(sbp + SM_IDX))[tid] = (r < N_NODES) ? __ldg(idx + r) : -1;
    }
    __syncthreads();

    // ---- MMA mainloop ----
    // A frag addr: groups L0-7: rows 0-7 k0 | L8-15: rows 8-15 k0 |
    //              L16-23: rows 0-7 k8 | L24-31: rows 8-15 k8
    uint32_t aOff = (uint32_t)((mr + (lane & 15)) * TSTRIDE + (lane >> 4) * 16);
    // B frag addr (x4 = n-tile pair): L0-7: n j k0 | L8-15: n j k8 |
    //              L16-23: n j+1 k0 | L24-31: n j+1 k8
    uint32_t bOff = (uint32_t)((nc + (lane & 7) + ((lane >> 4) << 3)) * TSTRIDE +
                               ((lane >> 3) & 1) * 16);
    uint32_t uAhi = sb + SM_AHI + aOff;
    uint32_t uAlo = sb + SM_ALO + aOff;
    uint32_t uBhi = sb + SM_BHI + bOff;
    uint32_t uBlo = sb + SM_BLO + bOff;

    float acc[2][8][4];
    #pragma unroll
    for (int i = 0; i < 2; i++)
        #pragma unroll
        for (int j = 0; j < 8; j++)
            #pragma unroll
            for (int e = 0; e < 4; e++) acc[i][j][e] = 0.f;

    #pragma unroll
    for (int ks = 0; ks < 8; ks++) {
        uint32_t kbB = ks * 32;          // 16 bf16 = 32 bytes
        uint32_t ah[2][4], al[2][4];
        ldm_x4(ah[0], uAhi + kbB);
        ldm_x4(ah[1], uAhi + 16 * TSTRIDE + kbB);
        ldm_x4(al[0], uAlo + kbB);
        ldm_x4(al[1], uAlo + 16 * TSTRIDE + kbB);
        #pragma unroll
        for (int jp = 0; jp < 4; jp++) {
            uint32_t bh[4], bl[4];
            ldm_x4(bh, uBhi + jp * 16 * TSTRIDE + kbB);
            ldm_x4(bl, uBlo + jp * 16 * TSTRIDE + kbB);
            int j0 = 2 * jp;
            #pragma unroll
            for (int i = 0; i < 2; i++) {
                mma_bf16(acc[i][j0],     ah[i], bh);       // Ah*Bh (n-tile j0)
                mma_bf16(acc[i][j0 + 1], ah[i], bh + 2);   //        (n-tile j0+1)
                mma_bf16(acc[i][j0],     ah[i], bl);       // Ah*Bl
                mma_bf16(acc[i][j0 + 1], ah[i], bl + 2);
                mma_bf16(acc[i][j0],     al[i], bh);       // Al*Bh
                mma_bf16(acc[i][j0 + 1], al[i], bh + 2);
            }
        }
    }

    // ---- epilogue ----
    int rq = lane >> 2;                  // 0..7
    int cp = 2 * (lane & 3);             // 0,2,4,6
    if (MODE == 0) {
        #pragma unroll
        for (int i = 0; i < 2; i++) {
            #pragma unroll
            for (int j = 0; j < 8; j++) {
                int col = nc + j * 8 + cp;
                float2 b = __ldg((const float2*)(bias + col));
                int r1 = row0 + mr + i * 16 + rq;
                int r2 = r1 + 8;
                if (r1 < N_NODES) {
                    float2 v;
                    v.x = fmaxf(acc[i][j][0] + b.x, 0.f);
                    v.y = fmaxf(acc[i][j][1] + b.y, 0.f);
                    *(float2*)(g_bufB + (size_t)r1 * D + col) = v;
                }
                if (r2 < N_NODES) {
                    float2 v;
                    v.x = fmaxf(acc[i][j][2] + b.x, 0.f);
                    v.y = fmaxf(acc[i][j][3] + b.y, 0.f);
                    *(float2*)(g_bufB + (size_t)r2 * D + col) = v;
                }
            }
        }
    } else {
        __syncthreads();                 // about to overwrite A region
        float* sOutf = (float*)sbp;      // 128 rows x stride 132 floats
        #pragma unroll
        for (int i = 0; i < 2; i++) {
            #pragma unroll
            for (int j = 0; j < 8; j++) {
                int col = nc + j * 8 + cp;
                float2 b = __ldg((const float2*)(bias + col));
                int rl1 = mr + i * 16 + rq;
                float2 v1, v2;
                v1.x = acc[i][j][0] + b.x;  v1.y = acc[i][j][1] + b.y;
                v2.x = acc[i][j][2] + b.x;  v2.y = acc[i][j][3] + b.y;
                *(float2*)(sOutf + rl1 * 132 + col) = v1;
                *(float2*)(sOutf + (rl1 + 8) * 132 + col) = v2;
            }
        }
        __syncthreads();
        const int* sIdx = (const int*)(sbp + SM_IDX);
        int c    = tid & 127;
        int half = tid >> 7;
        int rs = half * 64, re = rs + 64;
        float accp = 0.f;
        int cur = -1;
        for (int r = rs; r < re; r++) {
            int g = sIdx[r];
            if (g != cur) {
                if (cur >= 0) atomicAdd(&g_pooled[cur * D + c], accp);
                accp = 0.f;
                cur = g;
            }
            if (g >= 0) accp += sOutf[r * 132 + c];
        }
        if (cur >= 0) atomicAdd(&g_pooled[cur * D + c], accp);
    }
}

// ---------------------------------------------------------------------------
// BatchNorm stats over the 512 graphs (two-pass)
// ---------------------------------------------------------------------------
__global__ void bn_stats(const float* __restrict__ gamma,
                         const float* __restrict__ beta) {
    int c = threadIdx.x;
    float s = 0.f;
    #pragma unroll 8
    for (int r = 0; r < N_GRAPHS; r++) s += g_pooled[r * D + c];
    float mean = s * (1.f / N_GRAPHS);
    float ss = 0.f;
    #pragma unroll 8
    for (int r = 0; r < N_GRAPHS; r++) {
        float d = g_pooled[r * D + c] - mean;
        ss += d * d;
    }
    float var = ss * (1.f / N_GRAPHS);
    float sc = rsqrtf(var + BN_EPS) * gamma[c];
    g_scale[c] = sc;
    g_shift[c] = beta[c] - mean * sc;
}

// ---------------------------------------------------------------------------
// Head: BN-apply, relu(@W3+b3), @W4+b4, log_softmax. One block per graph.
// ---------------------------------------------------------------------------
__global__ void head(const float* __restrict__ W3, const float* __restrict__ b3,
                     const float* __restrict__ W4, const float* __restrict__ b4,
                     float* __restrict__ out) {
    int g = blockIdx.x;
    int c = threadIdx.x;
    __shared__ float sNb[D];
    __shared__ float sZg[D];
    __shared__ float sL[N_CLASS];
    __shared__ float sLse;

    float p = g_pooled[g * D + c];
    sNb[c] = p * g_scale[c] + g_shift[c];
    __syncthreads();

    float acc = b3[c];
    #pragma unroll 8
    for (int k = 0; k < D; k++) acc = fmaf(sNb[k], W3[(size_t)k * D + c], acc);
    sZg[c] = fmaxf(acc, 0.f);
    __syncthreads();

    if (c < N_CLASS) {
        float l = b4[c];
        #pragma unroll 8
        for (int k = 0; k < D; k++) l = fmaf(sZg[k], W4[(size_t)k * N_CLASS + c], l);
        sL[c] = l;
    }
    __syncthreads();

    if (c == 0) {
        float m = sL[0];
        #pragma unroll
        for (int i = 1; i < N_CLASS; i++) m = fmaxf(m, sL[i]);
        float se = 0.f;
        #pragma unroll
        for (int i = 0; i < N_CLASS; i++) se += expf(sL[i] - m);
        sLse = m + logf(se);
    }
    __syncthreads();

    if (c < N_CLASS) out[g * N_CLASS + c] = sL[c] - sLse;
}

// ---------------------------------------------------------------------------
extern "C" void kernel_launch(void* const* d_in, const int* in_sizes, int n_in,
                              void* d_out, int out_size) {
    const float* x     = (const float*)d_in[0];
    const int*   ei    = (const int*)d_in[1];
    const int*   idx   = (const int*)d_in[2];
    const float* W1    = (const float*)d_in[3];
    const float* b1    = (const float*)d_in[4];
    const float* W2    = (const float*)d_in[5];
    const float* b2    = (const float*)d_in[6];
    const float* W3    = (const float*)d_in[7];
    const float* b3    = (const float*)d_in[8];
    const float* W4    = (const float*)d_in[9];
    const float* b4    = (const float*)d_in[10];
    const float* gamma = (const float*)d_in[11];
    const float* beta  = (const float*)d_in[12];
    float* out = (float*)d_out;

    const int* src = ei;
    const int* dst = ei + N_EDGES;

    __nv_bfloat16* whi_dev; __nv_bfloat16* wlo_dev;
    cudaGetSymbolAddress((void**)&whi_dev, g_Whi);
    cudaGetSymbolAddress((void**)&wlo_dev, g_Wlo);

    cudaFuncSetAttribute(gemm_mma<0>, cudaFuncAttributeMaxDynamicSharedMemorySize, SMEM_MMA);
    cudaFuncSetAttribute(gemm_mma<1>, cudaFuncAttributeMaxDynamicSharedMemorySize, SMEM_MMA);

    const int aggBlocks  = (N_NODES + 7) / 8;
    const int eBlocks    = (N_EDGES + 511) / 512;
    const int tcBlocks   = (N_NODES + 127) / 128;   // 782

    // CSR build (once, serves both agg passes)
    zero_misc<<<(N_NODES + 255) / 256, 256>>>();
    hist_deg<<<eBlocks, 512>>>(dst);
    scan_l1<<<NSCAN, SCAN_BLK>>>();
    scan_l2<<<1, 256>>>();
    scan_l3<<<(N_NODES + 255) / 256, 256>>>();
    scatter_csr<<<eBlocks, 512>>>(src, dst);
    wprep<<<(2 * D * D + 255) / 256, 256>>>(W1, W2);

    // layer 1
    node_agg<0><<<aggBlocks, 256>>>(x);
    gemm_mma<0><<<tcBlocks, 256, SMEM_MMA>>>(whi_dev, wlo_dev, b1, nullptr);

    // layer 2 + pooling
    node_agg<1><<<aggBlocks, 256>>>(nullptr);
    gemm_mma<1><<<tcBlocks, 256, SMEM_MMA>>>(whi_dev + D * D, wlo_dev + D * D, b2, idx);

    // head
    bn_stats<<<1, 128>>>(gamma, beta);
    head<<<N_GRAPHS, 128>>>(W3, b3, W4, b4, out);
}

// round 10
// speedup vs baseline: 4.0860x; 1.2367x over previous
#include <cuda_runtime.h>
#include <cuda_bf16.h>
#include <math.h>
#include <stdint.h>

#define N_NODES  100000
#define N_EDGES  1600000
#define D        128
#define N_GRAPHS 512
#define N_CLASS  10
#define BN_EPS   1e-5f

#define NT   ((size_t)N_NODES * D)      // 12.8M floats
#define PAD_M 100032                    // 1563 * 64

#define SCAN_BLK 512
#define NSCAN    ((N_NODES + SCAN_BLK - 1) / SCAN_BLK)   // 196

// ---------------------------------------------------------------------------
// Scratch (allocation-free: __device__ globals)
// ---------------------------------------------------------------------------
__device__ float g_bufB[NT];            // z1 (fp32, gathered by agg pass 2)
__device__ __nv_bfloat16 g_Ahi[(size_t)PAD_M * D];   // pre-split agg output
__device__ __nv_bfloat16 g_Alo[(size_t)PAD_M * D];
__device__ float g_pooled[N_GRAPHS * D];
__device__ float g_scale[D];
__device__ float g_shift[D];

__device__ int g_deg[N_NODES];
__device__ int g_scan[N_NODES];
__device__ int g_bsum[NSCAN];
__device__ int g_boff[NSCAN];
__device__ int g_rowstart[N_NODES];
__device__ int g_cursor[N_NODES];
__device__ int g_csrsrc[N_EDGES];

// W split into bf16 hi/lo, n-major ([n][k]) — B operand for mma row.col
__device__ __nv_bfloat16 g_Whi[2][D * D];
__device__ __nv_bfloat16 g_Wlo[2][D * D];

// ---------------------------------------------------------------------------
// helpers
// ---------------------------------------------------------------------------
__device__ __forceinline__ uint32_t smem_to_u32(const void* p) {
    uint32_t a;
    asm("{ .reg .u64 t; cvta.to.shared.u64 t, %1; cvt.u32.u64 %0, t; }"
        : "=r"(a) : "l"(p));
    return a;
}
__device__ __forceinline__ void ldm_x4(uint32_t* r, uint32_t addr) {
    asm volatile("ldmatrix.sync.aligned.m8n8.x4.shared.b16 {%0,%1,%2,%3}, [%4];"
                 : "=r"(r[0]), "=r"(r[1]), "=r"(r[2]), "=r"(r[3]) : "r"(addr));
}
__device__ __forceinline__ void mma_bf16(float* c, const uint32_t* a,
                                         const uint32_t* b) {
    asm volatile(
        "mma.sync.aligned.m16n8k16.row.col.f32.bf16.bf16.f32 "
        "{%0,%1,%2,%3}, {%4,%5,%6,%7}, {%8,%9}, {%0,%1,%2,%3};"
        : "+f"(c[0]), "+f"(c[1]), "+f"(c[2]), "+f"(c[3])
        : "r"(a[0]), "r"(a[1]), "r"(a[2]), "r"(a[3]), "r"(b[0]), "r"(b[1]));
}
__device__ __forceinline__ uint32_t pkbf2(float a, float b) {
    __nv_bfloat162 t = __floats2bfloat162_rn(a, b);
    return *reinterpret_cast<uint32_t*>(&t);
}
__device__ __forceinline__ void cp16(uint32_t smem, const void* g) {
    asm volatile("cp.async.cg.shared.global [%0], [%1], 16;"
                 :: "r"(smem), "l"(g) : "memory");
}
#define CP_COMMIT() asm volatile("cp.async.commit_group;" ::: "memory")
#define CP_WAIT0()  asm volatile("cp.async.wait_group 0;" ::: "memory")

// ---------------------------------------------------------------------------
// CSR build
// ---------------------------------------------------------------------------
__global__ void zero_misc() {
    int i = blockIdx.x * blockDim.x + threadIdx.x;
    if (i < N_NODES) g_deg[i] = 0;
    if (i < N_GRAPHS * D) g_pooled[i] = 0.f;
}
__global__ void hist_deg(const int* __restrict__ dst) {
    int e = blockIdx.x * blockDim.x + threadIdx.x;
    if (e < N_EDGES) atomicAdd(&g_deg[dst[e]], 1);
}
__global__ __launch_bounds__(SCAN_BLK) void scan_l1() {
    __shared__ int s[SCAN_BLK];
    int t = threadIdx.x;
    int i = blockIdx.x * SCAN_BLK + t;
    int v = (i < N_NODES) ? g_deg[i] : 0;
    s[t] = v;
    __syncthreads();
    #pragma unroll
    for (int off = 1; off < SCAN_BLK; off <<= 1) {
        int add = (t >= off) ? s[t - off] : 0;
        __syncthreads();
        s[t] += add;
        __syncthreads();
    }
    if (i < N_NODES) g_scan[i] = s[t];
    if (t == SCAN_BLK - 1) g_bsum[blockIdx.x] = s[t];
}
__global__ __launch_bounds__(256) void scan_l2() {
    __shared__ int s[256];
    int t = threadIdx.x;
    int v = (t < NSCAN) ? g_bsum[t] : 0;
    s[t] = v;
    __syncthreads();
    #pragma unroll
    for (int off = 1; off < 256; off <<= 1) {
        int add = (t >= off) ? s[t - off] : 0;
        __syncthreads();
        s[t] += add;
        __syncthreads();
    }
    if (t < NSCAN) g_boff[t] = s[t] - v;
}
__global__ void scan_l3() {
    int i = blockIdx.x * blockDim.x + threadIdx.x;
    if (i < N_NODES) {
        int rs = g_scan[i] - g_deg[i] + g_boff[i / SCAN_BLK];
        g_rowstart[i] = rs;
        g_cursor[i] = rs;
    }
}
__global__ void scatter_csr(const int* __restrict__ src,
                            const int* __restrict__ dst) {
    int e = blockIdx.x * blockDim.x + threadIdx.x;
    if (e < N_EDGES) {
        int pos = atomicAdd(&g_cursor[dst[e]], 1);
        g_csrsrc[pos] = src[e];
    }
}

// ---------------------------------------------------------------------------
// W split: g_Whi/g_Wlo[layer][n][k] = bf16 hi/lo of W[k][n]
// ---------------------------------------------------------------------------
__global__ void wprep(const float* __restrict__ W1, const float* __restrict__ W2) {
    int i = blockIdx.x * blockDim.x + threadIdx.x;
    if (i >= 2 * D * D) return;
    int layer = i >> 14;
    int k = (i >> 7) & 127;
    int n = i & 127;
    float v = (layer ? W2 : W1)[k * D + n];
    __nv_bfloat16 hi = __float2bfloat16_rn(v);
    float lo = v - __bfloat162float(hi);
    g_Whi[layer][n * D + k] = hi;
    g_Wlo[layer][n * D + k] = __float2bfloat16_rn(lo);
}

// ---------------------------------------------------------------------------
// Gather aggregation + bf16 hi/lo split: writes g_Ahi/g_Alo (MMA-ready).
// One warp per (padded) node. SRC==0: gather x. SRC==1: gather g_bufB (z1).
// ---------------------------------------------------------------------------
template<int SRC>
__global__ __launch_bounds__(256)
void node_agg(const float* __restrict__ hext) {
    int n = blockIdx.x * 8 + (threadIdx.x >> 5);
    if (n >= PAD_M) return;
    int lane = threadIdx.x & 31;
    uint2* ohi = (uint2*)(g_Ahi + (size_t)n * D) + lane;
    uint2* olo = (uint2*)(g_Alo + (size_t)n * D) + lane;

    if (n >= N_NODES) {
        *ohi = make_uint2(0, 0);
        *olo = make_uint2(0, 0);
        return;
    }
    const float4* h4 = (const float4*)((SRC == 0) ? hext : (const float*)g_bufB);

    float4 acc  = __ldg(h4 + (size_t)n * 32 + lane);
    float4 acc2 = make_float4(0.f, 0.f, 0.f, 0.f);

    int s0 = g_rowstart[n];
    int e0 = s0 + g_deg[n];
    for (int base = s0; base < e0; base += 32) {
        int cnt = min(32, e0 - base);
        int sv = (lane < cnt) ? __ldg(g_csrsrc + base + lane) : 0;
        int j = 0;
        for (; j + 1 < cnt; j += 2) {
            int sa = __shfl_sync(0xffffffffu, sv, j);
            int sb = __shfl_sync(0xffffffffu, sv, j + 1);
            float4 va = __ldg(h4 + (size_t)sa * 32 + lane);
            float4 vb = __ldg(h4 + (size_t)sb * 32 + lane);
            acc.x += va.x;  acc.y += va.y;  acc.z += va.z;  acc.w += va.w;
            acc2.x += vb.x; acc2.y += vb.y; acc2.z += vb.z; acc2.w += vb.w;
        }
        if (j < cnt) {
            int sa = __shfl_sync(0xffffffffu, sv, j);
            float4 va = __ldg(h4 + (size_t)sa * 32 + lane);
            acc.x += va.x; acc.y += va.y; acc.z += va.z; acc.w += va.w;
        }
    }
    float f[4] = {acc.x + acc2.x, acc.y + acc2.y, acc.z + acc2.z, acc.w + acc2.w};
    float fh[4], fl[4];
    #pragma unroll
    for (int e = 0; e < 4; e++) {
        __nv_bfloat16 h = __float2bfloat16_rn(f[e]);
        fh[e] = __bfloat162float(h);
        fl[e] = f[e] - fh[e];
    }
    *ohi = make_uint2(pkbf2(fh[0], fh[1]), pkbf2(fh[2], fh[3]));
    *olo = make_uint2(pkbf2(fl[0], fl[1]), pkbf2(fl[2], fl[3]));
}

// ---------------------------------------------------------------------------
// Tensor-core GEMM via mma.sync (bf16 split-3, f32 accum).
// Block: 64 rows x 128 cols, 256 threads = 8 warps (2 m x 4 n), warp m32xn32.
// A pre-split (g_Ahi/g_Alo), staged via cp.async. 104.4KB smem -> 2 CTA/SM.
// MODE 0: relu(D + bias) -> g_bufB.  MODE 1: (D+bias) segment-pool -> g_pooled
// ---------------------------------------------------------------------------
#define TSTRIDE 272
#define SM_AHI 0
#define SM_ALO 17408
#define SM_BHI 34816
#define SM_BLO 69632
#define SM_IDX 104448
#define SMEM_MMA (104448 + 512)

template<int MODE>
__global__ __launch_bounds__(256, 2)
void gemm_mma(const __nv_bfloat16* __restrict__ Whi,
              const __nv_bfloat16* __restrict__ Wlo,
              const float* __restrict__ bias,
              const int* __restrict__ idx) {
    extern __shared__ __align__(16) char sbp[];
    uint32_t sb = smem_to_u32(sbp);

    int tid  = threadIdx.x;
    int wid  = tid >> 5;
    int lane = tid & 31;
    int row0 = blockIdx.x * 64;
    int mr = (wid >> 2) * 32;            // warp row base (0,32)
    int nc = (wid & 3) * 32;             // warp col base (0,32,64,96)

    // ---- stage A hi/lo (64 rows x 256B each) via cp.async ----
    #pragma unroll
    for (int q = 0; q < 4; q++) {
        int e = tid + q * 256;           // 0..1023
        int row = e >> 4;
        int ch  = e & 15;
        const __nv_bfloat16* gh = g_Ahi + (size_t)(row0 + row) * D + ch * 8;
        const __nv_bfloat16* gl = g_Alo + (size_t)(row0 + row) * D + ch * 8;
        cp16(sb + SM_AHI + row * TSTRIDE + ch * 16, gh);
        cp16(sb + SM_ALO + row * TSTRIDE + ch * 16, gl);
    }
    // ---- stage B hi/lo (128 rows x 256B each) via cp.async ----
    #pragma unroll
    for (int q = 0; q < 8; q++) {
        int e = tid + q * 256;           // 0..2047
        int row = e >> 4;
        int ch  = e & 15;
        cp16(sb + SM_BHI + row * TSTRIDE + ch * 16, Whi + row * D + ch * 8);
        cp16(sb + SM_BLO + row * TSTRIDE + ch * 16, Wlo + row * D + ch * 8);
    }
    CP_COMMIT();
    if (MODE == 1 && tid < 64) {
        int r = row0 + tid;
        ((int*)(sbp + SM_IDX))[tid] = (r < N_NODES) ? __ldg(idx + r) : -1;
    }
    CP_WAIT0();
    __syncthreads();

    // ---- fragment addresses ----
    uint32_t aOff = (uint32_t)((mr + (lane & 15)) * TSTRIDE + (lane >> 4) * 16);
    uint32_t bOff = (uint32_t)((nc + (lane & 7) + ((lane >> 4) << 3)) * TSTRIDE +
                               ((lane >> 3) & 1) * 16);
    uint32_t uAhi = sb + SM_AHI + aOff;
    uint32_t uAlo = sb + SM_ALO + aOff;
    uint32_t uBhi = sb + SM_BHI + bOff;
    uint32_t uBlo = sb + SM_BLO + bOff;

    float acc[2][4][4];
    #pragma unroll
    for (int i = 0; i < 2; i++)
        #pragma unroll
        for (int j = 0; j < 4; j++)
            #pragma unroll
            for (int e = 0; e < 4; e++) acc[i][j][e] = 0.f;

    #pragma unroll
    for (int ks = 0; ks < 8; ks++) {
        uint32_t kbB = ks * 32;          // 16 bf16 = 32 bytes
        uint32_t ah[2][4], al[2][4];
        ldm_x4(ah[0], uAhi + kbB);
        ldm_x4(ah[1], uAhi + 16 * TSTRIDE + kbB);
        ldm_x4(al[0], uAlo + kbB);
        ldm_x4(al[1], uAlo + 16 * TSTRIDE + kbB);
        #pragma unroll
        for (int jp = 0; jp < 2; jp++) {
            uint32_t bh[4], bl[4];
            ldm_x4(bh, uBhi + jp * 16 * TSTRIDE + kbB);
            ldm_x4(bl, uBlo + jp * 16 * TSTRIDE + kbB);
            int j0 = 2 * jp;
            #pragma unroll
            for (int i = 0; i < 2; i++) {
                mma_bf16(acc[i][j0],     ah[i], bh);
                mma_bf16(acc[i][j0 + 1], ah[i], bh + 2);
                mma_bf16(acc[i][j0],     ah[i], bl);
                mma_bf16(acc[i][j0 + 1], ah[i], bl + 2);
                mma_bf16(acc[i][j0],     al[i], bh);
                mma_bf16(acc[i][j0 + 1], al[i], bh + 2);
            }
        }
    }

    // ---- epilogue ----
    int rq = lane >> 2;                  // 0..7
    int cp = 2 * (lane & 3);             // 0,2,4,6
    if (MODE == 0) {
        #pragma unroll
        for (int i = 0; i < 2; i++) {
            #pragma unroll
            for (int j = 0; j < 4; j++) {
                int col = nc + j * 8 + cp;
                float2 b = __ldg((const float2*)(bias + col));
                int r1 = row0 + mr + i * 16 + rq;
                int r2 = r1 + 8;
                if (r1 < N_NODES) {
                    float2 v;
                    v.x = fmaxf(acc[i][j][0] + b.x, 0.f);
                    v.y = fmaxf(acc[i][j][1] + b.y, 0.f);
                    *(float2*)(g_bufB + (size_t)r1 * D + col) = v;
                }
                if (r2 < N_NODES) {
                    float2 v;
                    v.x = fmaxf(acc[i][j][2] + b.x, 0.f);
                    v.y = fmaxf(acc[i][j][3] + b.y, 0.f);
                    *(float2*)(g_bufB + (size_t)r2 * D + col) = v;
                }
            }
        }
    } else {
        __syncthreads();                 // about to overwrite A region
        float* sOutf = (float*)sbp;      // 64 rows x stride 132 floats
        #pragma unroll
        for (int i = 0; i < 2; i++) {
            #pragma unroll
            for (int j = 0; j < 4; j++) {
                int col = nc + j * 8 + cp;
                float2 b = __ldg((const float2*)(bias + col));
                int rl1 = mr + i * 16 + rq;
                float2 v1, v2;
                v1.x = acc[i][j][0] + b.x;  v1.y = acc[i][j][1] + b.y;
                v2.x = acc[i][j][2] + b.x;  v2.y = acc[i][j][3] + b.y;
                *(float2*)(sOutf + rl1 * 132 + col) = v1;
                *(float2*)(sOutf + (rl1 + 8) * 132 + col) = v2;
            }
        }
        __syncthreads();
        const int* sIdx = (const int*)(sbp + SM_IDX);
        int c    = tid & 127;
        int half = tid >> 7;
        int rs = half * 32, re = rs + 32;
        float accp = 0.f;
        int cur = -1;
        for (int r = rs; r < re; r++) {
            int g = sIdx[r];
            if (g != cur) {
                if (cur >= 0) atomicAdd(&g_pooled[cur * D + c], accp);
                accp = 0.f;
                cur = g;
            }
            if (g >= 0) accp += sOutf[r * 132 + c];
        }
        if (cur >= 0) atomicAdd(&g_pooled[cur * D + c], accp);
    }
}

// ---------------------------------------------------------------------------
// BatchNorm stats over the 512 graphs (two-pass)
// ---------------------------------------------------------------------------
__global__ void bn_stats(const float* __restrict__ gamma,
                         const float* __restrict__ beta) {
    int c = threadIdx.x;
    float s = 0.f;
    #pragma unroll 8
    for (int r = 0; r < N_GRAPHS; r++) s += g_pooled[r * D + c];
    float mean = s * (1.f / N_GRAPHS);
    float ss = 0.f;
    #pragma unroll 8
    for (int r = 0; r < N_GRAPHS; r++) {
        float d = g_pooled[r * D + c] - mean;
        ss += d * d;
    }
    float var = ss * (1.f / N_GRAPHS);
    float sc = rsqrtf(var + BN_EPS) * gamma[c];
    g_scale[c] = sc;
    g_shift[c] = beta[c] - mean * sc;
}

// ---------------------------------------------------------------------------
// Head: BN-apply, relu(@W3+b3), @W4+b4, log_softmax. One block per graph.
// ---------------------------------------------------------------------------
__global__ void head(const float* __restrict__ W3, const float* __restrict__ b3,
                     const float* __restrict__ W4, const float* __restrict__ b4,
                     float* __restrict__ out) {
    int g = blockIdx.x;
    int c = threadIdx.x;
    __shared__ float sNb[D];
    __shared__ float sZg[D];
    __shared__ float sL[N_CLASS];
    __shared__ float sLse;

    float p = g_pooled[g * D + c];
    sNb[c] = p * g_scale[c] + g_shift[c];
    __syncthreads();

    float acc = b3[c];
    #pragma unroll 8
    for (int k = 0; k < D; k++) acc = fmaf(sNb[k], W3[(size_t)k * D + c], acc);
    sZg[c] = fmaxf(acc, 0.f);
    __syncthreads();

    if (c < N_CLASS) {
        float l = b4[c];
        #pragma unroll 8
        for (int k = 0; k < D; k++) l = fmaf(sZg[k], W4[(size_t)k * N_CLASS + c], l);
        sL[c] = l;
    }
    __syncthreads();

    if (c == 0) {
        float m = sL[0];
        #pragma unroll
        for (int i = 1; i < N_CLASS; i++) m = fmaxf(m, sL[i]);
        float se = 0.f;
        #pragma unroll
        for (int i = 0; i < N_CLASS; i++) se += expf(sL[i] - m);
        sLse = m + logf(se);
    }
    __syncthreads();

    if (c < N_CLASS) out[g * N_CLASS + c] = sL[c] - sLse;
}

// ---------------------------------------------------------------------------
extern "C" void kernel_launch(void* const* d_in, const int* in_sizes, int n_in,
                              void* d_out, int out_size) {
    const float* x     = (const float*)d_in[0];
    const int*   ei    = (const int*)d_in[1];
    const int*   idx   = (const int*)d_in[2];
    const float* W1    = (const float*)d_in[3];
    const float* b1    = (const float*)d_in[4];
    const float* W2    = (const float*)d_in[5];
    const float* b2    = (const float*)d_in[6];
    const float* W3    = (const float*)d_in[7];
    const float* b3    = (const float*)d_in[8];
    const float* W4    = (const float*)d_in[9];
    const float* b4    = (const float*)d_in[10];
    const float* gamma = (const float*)d_in[11];
    const float* beta  = (const float*)d_in[12];
    float* out = (float*)d_out;

    const int* src = ei;
    const int* dst = ei + N_EDGES;

    __nv_bfloat16* whi_dev; __nv_bfloat16* wlo_dev;
    cudaGetSymbolAddress((void**)&whi_dev, g_Whi);
    cudaGetSymbolAddress((void**)&wlo_dev, g_Wlo);

    cudaFuncSetAttribute(gemm_mma<0>, cudaFuncAttributeMaxDynamicSharedMemorySize, SMEM_MMA);
    cudaFuncSetAttribute(gemm_mma<1>, cudaFuncAttributeMaxDynamicSharedMemorySize, SMEM_MMA);

    const int aggBlocks  = (PAD_M + 7) / 8;         // 12504
    const int eBlocks    = (N_EDGES + 511) / 512;
    const int tcBlocks   = PAD_M / 64;              // 1563

    // CSR build (once, serves both agg passes)
    zero_misc<<<(N_NODES + 255) / 256, 256>>>();
    hist_deg<<<eBlocks, 512>>>(dst);
    scan_l1<<<NSCAN, SCAN_BLK>>>();
    scan_l2<<<1, 256>>>();
    scan_l3<<<(N_NODES + 255) / 256, 256>>>();
    scatter_csr<<<eBlocks, 512>>>(src, dst);
    wprep<<<(2 * D * D + 255) / 256, 256>>>(W1, W2);

    // layer 1
    node_agg<0><<<aggBlocks, 256>>>(x);
    gemm_mma<0><<<tcBlocks, 256, SMEM_MMA>>>(whi_dev, wlo_dev, b1, nullptr);

    // layer 2 + pooling
    node_agg<1><<<aggBlocks, 256>>>(nullptr);
    gemm_mma<1><<<tcBlocks, 256, SMEM_MMA>>>(whi_dev + D * D, wlo_dev + D * D, b2, idx);

    // head
    bn_stats<<<1, 128>>>(gamma, beta);
    head<<<N_GRAPHS, 128>>>(W3, b3, W4, b4, out);
}